// round 16
// baseline (speedup 1.0000x reference)
#include <cuda_runtime.h>
#include <math.h>

#define EE 25440
#define NN 160

typedef unsigned long long ull;

// ---------------- packed f32x2 helpers ----------------
__device__ __forceinline__ ull ffma2u(ull a, ull b, ull c) {
    ull d;
    asm("fma.rn.f32x2 %0, %1, %2, %3;" : "=l"(d) : "l"(a), "l"(b), "l"(c));
    return d;
}
__device__ __forceinline__ ull fdup(float v) {
    ull d;
    asm("mov.b64 %0, {%1, %1};" : "=l"(d) : "r"(__float_as_uint(v)));
    return d;
}
__device__ __forceinline__ ull fpack(float lo, float hi) {
    ull d;
    asm("mov.b64 %0, {%1, %2};" : "=l"(d) : "f"(lo), "f"(hi));
    return d;
}
__device__ __forceinline__ float2 unpack2(ull v) {
    float2 r;
    asm("mov.b64 {%0, %1}, %2;" : "=f"(r.x), "=f"(r.y) : "l"(v));
    return r;
}
__device__ __forceinline__ unsigned smem_u32(const void* p) {
    unsigned a;
    asm("{ .reg .u64 t; cvta.to.shared.u64 t, %1; cvt.u32.u64 %0, t; }" : "=r"(a) : "l"(p));
    return a;
}
__device__ __forceinline__ void cp16(unsigned dst, const void* src) {
    asm volatile("cp.async.ca.shared.global [%0], [%1], 16;" :: "r"(dst), "l"(src));
}
__device__ __forceinline__ void cp4(unsigned dst, const void* src) {
    asm volatile("cp.async.ca.shared.global [%0], [%1], 4;" :: "r"(dst), "l"(src));
}
#define CP_COMMIT() asm volatile("cp.async.commit_group;" ::: "memory")
#define CP_WAIT0()  asm volatile("cp.async.wait_group 0;" ::: "memory")

// ---------------- device scratch (static, no runtime alloc) ----------------
__device__ float g_x_ii[NN * 1568];
__device__ float g_x_ij[(size_t)EE * 1568];
__device__ float g_h_ii_c[NN * 128], g_h_ii_b[NN * 128];
__device__ float g_h_ij_c[EE * 128], g_h_ij_b[EE * 128];
__device__ float g_w_ii[NN * 1792];
__device__ float g_w_ij[(size_t)EE * 1792];
__device__ float g_b_ii[NN * 14], g_b_ij[EE * 14];
__device__ float g_raw_ii[NN * 196];
__device__ float g_raw_ij[EE * 196];
__device__ float4 g_w3j4[307];     // 1228 floats (1225 used, padded for float4)

// ---------------- constant tables ----------------
// feature irreps: l = {0,1,1,2,2,3,3,4,4}
__constant__ int c_XO[10] = {0, 32, 128, 224, 384, 544, 768, 992, 1280, 1568};
__constant__ int c_FO[9]  = {0, 64, 256, 448, 768, 1088, 1536, 1984, 2560};
__constant__ int c_D[9]   = {1, 3, 3, 5, 5, 7, 7, 9, 9};
__constant__ int c_MUL[3] = {3, 2, 1};   // out irrep multiplicities (index = l)
// o3 task table: 4*d tasks per segment (o-octs), cumulative
__constant__ int c_TB8[10] = {0, 4, 16, 28, 48, 68, 96, 124, 160, 196};

// 19 expansion paths, in reference INSTR order
__constant__ int P_I[19]  = {0,0,0,1,1,1,1,2,2,3,3,4,4,4,4,5,5,6,8};
__constant__ int P_J[19]  = {0,1,2,0,1,1,2,1,2,1,2,0,1,2,2,1,2,2,2};
__constant__ int P_K[19]  = {0,1,2,1,0,2,1,1,2,2,1,2,1,0,2,2,1,2,2};
__constant__ int P_WI[19] = {0,288,416,448,640,832,896,960,1088,1120,1184,1248,1344,1472,1568,1600,1664,1728,1760};
__constant__ int P_RO[19] = {0,9,13,14,32,50,56,62,74,77,87,97,112,132,147,152,166,180,187};
__constant__ int P_BO[19] = {0,9,13,-1,-1,-1,-1,-1,-1,-1,-1,-1,-1,-1,-1,-1,-1,-1,-1};
// wigner tensor (lj,lk,li), flat offsets
__constant__ int K_OFF[19]= {0,1,10,35,44,53,98,143,170,245,320,395,420,465,490,615,720,825,1000};
__constant__ int K_L3[19] = {0,0,0,1,1,1,1,1,1,2,2,2,2,2,2,3,3,3,4};  // li per path
__constant__ int W_L1[19] = {0,1,2,0,1,1,2,1,2,1,2,0,1,2,2,1,2,2,2};  // lj per path
__constant__ int W_L2[19] = {0,1,2,1,0,2,1,1,2,2,1,2,1,0,2,2,1,2,2};  // lk per path

// ---------------- Wigner 3j on device (fp64, exact port of reference) -----
struct cplx { double re, im; };

__device__ __forceinline__ double dfac(int n) {
    double r = 1.0;
    for (int i = 2; i <= n; i++) r *= (double)i;
    return r;
}

__device__ double su2_cg(int j1, int m1, int j2, int m2, int j3, int m3) {
    int vmin = max(max(j2 - j1 + m3, m1 - j1), 0);
    int vmax = min(min(j2 + j3 + m1, j3 - j1 + j2), j3 + m3);
    if (vmax < vmin) return 0.0;
    double c = sqrt((2.0 * j3 + 1.0) * dfac(j3 + j1 - j2) * dfac(j3 - j1 + j2) * dfac(j1 + j2 - j3)
                    * dfac(j3 + m3) * dfac(j3 - m3)
                    / (dfac(j1 + j2 + j3 + 1) * dfac(j1 - m1) * dfac(j1 + m1)
                       * dfac(j2 - m2) * dfac(j2 + m2)));
    double s = 0.0;
    for (int v = vmin; v <= vmax; v++) {
        double t = dfac(j2 + j3 + m1 - v) * dfac(j1 - m1 + v)
                   / (dfac(v) * dfac(j3 - j1 + j2 - v) * dfac(j3 + m3 - v) * dfac(v + j1 - j2 - m3));
        s += (((v + j2 + m2) & 1) ? -t : t);
    }
    return c * s;
}

// q(l)[row][col] including the (-i)^l factor
__device__ cplx q_entry(int l, int row, int col) {
    int m = row - l;
    const double r2 = 0.70710678118654752440;
    double re = 0.0, im = 0.0;
    if (m < 0) {
        if (col == l - m) re = r2;
        else if (col == l + m) im = -r2;
    } else if (m == 0) {
        if (col == l) re = 1.0;
    } else {
        double sg = (m & 1) ? -1.0 : 1.0;
        if (col == l + m) re = sg * r2;
        else if (col == l - m) im = sg * r2;
    }
    double a = re, b = im;
    switch (l & 3) {              // multiply by (-i)^l
        case 0: break;
        case 1: { double t = a; a = b;  b = -t; } break;
        case 2: a = -a; b = -b; break;
        case 3: { double t = a; a = -b; b = t; } break;
    }
    cplx q; q.re = a; q.im = b; return q;
}

__global__ void k_wigner() {
    int p = blockIdx.x;
    int l1 = W_L1[p], l2 = W_L2[p], l3 = K_L3[p];
    int d1 = 2 * l1 + 1, d2 = 2 * l2 + 1, d3 = 2 * l3 + 1;
    int nout = d1 * d2 * d3;
    double inv = 1.0 / sqrt(2.0 * l3 + 1.0);
    float* w3 = (float*)g_w3j4;
    for (int o = threadIdx.x; o < nout; o += blockDim.x) {
        int j = o / (d2 * d3);
        int rem = o % (d2 * d3);
        int lc = rem / d3;
        int m = rem % d3;
        // q(l)[row][col] is nonzero only for row in {col, 2l-col}
        int ic[2] = { j, d1 - 1 - j };
        int kc[2] = { lc, d2 - 1 - lc };
        int ni = (ic[1] == ic[0]) ? 1 : 2;
        int nk = (kc[1] == kc[0]) ? 1 : 2;
        double acc = 0.0;
        for (int ii = 0; ii < ni; ii++)
            for (int kk = 0; kk < nk; kk++) {
                int i = ic[ii], k = kc[kk];
                int n = i + k - l1 - l2 + l3;     // m3 = m1 + m2
                if (n < 0 || n >= d3) continue;
                double cg = su2_cg(l1, i - l1, l2, k - l2, l3, i - l1 + k - l2);
                if (cg == 0.0) continue;
                cplx q1 = q_entry(l1, i, j);
                cplx q2 = q_entry(l2, k, lc);
                cplx q3 = q_entry(l3, n, m);
                q3.im = -q3.im;                   // conj
                double re12 = q1.re * q2.re - q1.im * q2.im;
                double im12 = q1.re * q2.im + q1.im * q2.re;
                double re = re12 * q3.re - im12 * q3.im;
                acc += re * cg;
            }
        w3[K_OFF[p] + o] = (float)(acc * inv);
    }
}

// ---------------- o3 linear: x = blockdiag(W) @ f * (1/8) ------------------
// Row-blocked R=4 (verified: 416 -> 246us): each W LDS.128 pair amortized
// over 4 rows; f row-blocks staged by cp.async, double-buffered.
__global__ __launch_bounds__(224) void k_o3(const float* __restrict__ f,
                                            const float* __restrict__ W,
                                            int which, int nrows) {
    extern __shared__ float sh[];
    float* Wsh = sh;                               // 18432 floats
    float* fb0 = sh + 18432;                       // 4*3136 floats
    float* fb1 = sh + 18432 + 4 * 3136;            // 4*3136 floats
    for (int t = threadIdx.x; t < 4608; t += 224)
        ((float4*)Wsh)[t] = ((const float4*)W)[t];
    float* xbase = which ? g_x_ij : g_x_ii;

    int t = threadIdx.x;
    int s = 0;
    if (t < 196) { while (s < 8 && t >= c_TB8[s + 1]) s++; }
    int loc = t - c_TB8[s];
    int q = loc & 3;          // o-oct
    int m = loc >> 2;
    int d = c_D[s];
    int foff = c_FO[s] + m;

    unsigned fba[2] = { smem_u32(fb0), smem_u32(fb1) };
    float* fbp[2] = { fb0, fb1 };

    // prefetch row-block rb into buffer bi (14 cp.async per thread)
    auto prefetch = [&](int rb, int bi) {
        unsigned base = fba[bi];
        #pragma unroll
        for (int i = 0; i < 14; i++) {
            int slot = t + i * 224;               // 0..3135
            int r = slot / 784, pos = slot - r * 784;
            int row = rb * 4 + r;
            if (row < nrows)
                cp16(base + r * 12544 + pos * 16,
                     (const float4*)(f + (size_t)row * 3136) + pos);
        }
    };

    int rb = blockIdx.x;
    prefetch(rb, 0);
    CP_COMMIT();
    CP_WAIT0();
    __syncthreads();
    int cur = 0;
    for (; rb * 4 < nrows; rb += gridDim.x) {
        int rbn = rb + gridDim.x;
        if (rbn * 4 < nrows) { prefetch(rbn, cur ^ 1); CP_COMMIT(); }
        if (t < 196) {
            const float* fc = fbp[cur];
            const ulonglong2* w2p = (const ulonglong2*)(Wsh + s * 2048) + q * 2;
            ull a00=0,a01=0,a02=0,a03=0, a10=0,a11=0,a12=0,a13=0;
            ull a20=0,a21=0,a22=0,a23=0, a30=0,a31=0,a32=0,a33=0;
            #pragma unroll 2
            for (int u = 0; u < 64; u++) {
                ulonglong2 wa = w2p[u * 8];
                ulonglong2 wb = w2p[u * 8 + 1];
                int fo = foff + u * d;
                ull f0 = fdup(fc[fo]);
                ull f1 = fdup(fc[3136 + fo]);
                ull f2 = fdup(fc[6272 + fo]);
                ull f3 = fdup(fc[9408 + fo]);
                a00 = ffma2u(f0, wa.x, a00); a01 = ffma2u(f0, wa.y, a01);
                a02 = ffma2u(f0, wb.x, a02); a03 = ffma2u(f0, wb.y, a03);
                a10 = ffma2u(f1, wa.x, a10); a11 = ffma2u(f1, wa.y, a11);
                a12 = ffma2u(f1, wb.x, a12); a13 = ffma2u(f1, wb.y, a13);
                a20 = ffma2u(f2, wa.x, a20); a21 = ffma2u(f2, wa.y, a21);
                a22 = ffma2u(f2, wb.x, a22); a23 = ffma2u(f2, wb.y, a23);
                a30 = ffma2u(f3, wa.x, a30); a31 = ffma2u(f3, wa.y, a31);
                a32 = ffma2u(f3, wb.x, a32); a33 = ffma2u(f3, wb.y, a33);
            }
            int o0 = q * 8;
            ull accs[4][4] = {{a00,a01,a02,a03},{a10,a11,a12,a13},
                              {a20,a21,a22,a23},{a30,a31,a32,a33}};
            #pragma unroll
            for (int r = 0; r < 4; r++) {
                int row = rb * 4 + r;
                if (row < nrows) {
                    float* xp = xbase + (size_t)row * 1568 + c_XO[s] + m;
                    float2 r0 = unpack2(accs[r][0]), r1 = unpack2(accs[r][1]);
                    float2 r2 = unpack2(accs[r][2]), r3 = unpack2(accs[r][3]);
                    xp[(o0 + 0) * d] = r0.x * 0.125f;
                    xp[(o0 + 1) * d] = r0.y * 0.125f;
                    xp[(o0 + 2) * d] = r1.x * 0.125f;
                    xp[(o0 + 3) * d] = r1.y * 0.125f;
                    xp[(o0 + 4) * d] = r2.x * 0.125f;
                    xp[(o0 + 5) * d] = r2.y * 0.125f;
                    xp[(o0 + 6) * d] = r3.x * 0.125f;
                    xp[(o0 + 7) * d] = r3.y * 0.125f;
                }
            }
        }
        CP_WAIT0();
        __syncthreads();
        cur ^= 1;
    }
}

// ---------------- MLP hidden layers ----------------------------------------
__device__ __forceinline__ float silu(float v) { return v / (1.f + expf(-v)); }

__global__ __launch_bounds__(256) void k_mlp_ii(const float* __restrict__ embed,
        const float* __restrict__ w1c, const float* __restrict__ b1c,
        const float* __restrict__ w1b, const float* __restrict__ b1b) {
    __shared__ float esh[128];
    int b = blockIdx.x;
    if (threadIdx.x < 128) esh[threadIdx.x] = embed[b * 128 + threadIdx.x];
    __syncthreads();
    int c = threadIdx.x & 127, sel = threadIdx.x >> 7;
    const float* Wm = sel ? w1b : w1c;
    float acc = (sel ? b1b : b1c)[c];
    for (int k = 0; k < 128; k++) acc += esh[k] * Wm[k * 128 + c];
    float* out = sel ? g_h_ii_b : g_h_ii_c;
    out[b * 128 + c] = silu(acc);
}

__global__ __launch_bounds__(256) void k_mlp_ij(const float* __restrict__ embed,
        const float* __restrict__ w1c, const float* __restrict__ b1c,
        const float* __restrict__ w1b, const float* __restrict__ b1b) {
    __shared__ float Psh[32][256];
    int e0 = blockIdx.x * 32;
    for (int idx = threadIdx.x; idx < 32 * 256; idx += 256) {
        int e = idx >> 8, k = idx & 255;
        int ge = e0 + e;
        int s = ge / 159, rm = ge - s * 159;
        int dn = rm + (rm >= s);
        Psh[e][k] = (k < 128) ? embed[s * 128 + k] : embed[dn * 128 + (k - 128)];
    }
    __syncthreads();
    int c = threadIdx.x & 127, sel = threadIdx.x >> 7;
    const float* Wm = sel ? w1b : w1c;
    float bv = (sel ? b1b : b1c)[c];
    ull acc[32];
    #pragma unroll
    for (int e = 0; e < 32; e++) acc[e] = 0ULL;
    #pragma unroll 2
    for (int k = 0; k < 256; k += 4) {
        ull w0 = fpack(Wm[k * 128 + c],       Wm[(k + 1) * 128 + c]);
        ull w1 = fpack(Wm[(k + 2) * 128 + c], Wm[(k + 3) * 128 + c]);
        #pragma unroll
        for (int e = 0; e < 32; e++) {
            ulonglong2 p = *(const ulonglong2*)&Psh[e][k];
            acc[e] = ffma2u(p.x, w0, acc[e]);
            acc[e] = ffma2u(p.y, w1, acc[e]);
        }
    }
    float* out = sel ? g_h_ij_b : g_h_ij_c;
    #pragma unroll
    for (int e = 0; e < 32; e++) {
        float2 r = unpack2(acc[e]);
        out[(size_t)(e0 + e) * 128 + c] = silu(r.x + r.y + bv);
    }
}

// ---------------- second MLP layer: weights = H @ W2 + b2 ------------------
// Block 64 rows x 128 cols; thread = 16 rows x 2 cols.
__global__ __launch_bounds__(256) void k_w2(const float* __restrict__ W2,
                                            const float* __restrict__ b2,
                                            int nrows, int which) {
    extern __shared__ float s2[];
    float* Hsh = s2;                       // 64*128 floats (32 KB)
    ull* Wp = (ull*)(s2 + 64 * 128);       // [64 kp][128 c] packed pairs (64 KB)
    const float* H = which ? g_h_ij_c : g_h_ii_c;
    float* out = which ? g_w_ij : g_w_ii;
    int r0 = blockIdx.x * 64, c0 = blockIdx.y * 128;
    for (int idx = threadIdx.x; idx < 64 * 32; idx += 256) {
        int r = idx >> 5, qq = idx & 31;
        int gr = r0 + r;
        float4 v = make_float4(0.f, 0.f, 0.f, 0.f);
        if (gr < nrows) v = ((const float4*)(H + (size_t)gr * 128))[qq];
        ((float4*)(Hsh + r * 128))[qq] = v;
    }
    for (int idx = threadIdx.x; idx < 8192; idx += 256) {
        int kp = idx >> 7, c = idx & 127;
        float lo = W2[(size_t)(2 * kp) * 1792 + c0 + c];
        float hi = W2[(size_t)(2 * kp + 1) * 1792 + c0 + c];
        Wp[kp * 128 + c] = fpack(lo, hi);
    }
    __syncthreads();
    int c = threadIdx.x & 63, eg = threadIdx.x >> 6;
    ull acc0[16], acc1[16];
    #pragma unroll
    for (int i = 0; i < 16; i++) { acc0[i] = 0ULL; acc1[i] = 0ULL; }
    const float* hbase = Hsh + eg * 16 * 128;
    #pragma unroll 2
    for (int kp = 0; kp < 64; kp += 2) {
        ull w0a = Wp[kp * 128 + c];
        ull w1a = Wp[(kp + 1) * 128 + c];
        ull w0b = Wp[kp * 128 + c + 64];
        ull w1b = Wp[(kp + 1) * 128 + c + 64];
        #pragma unroll
        for (int i = 0; i < 16; i++) {
            ulonglong2 h = *(const ulonglong2*)(hbase + i * 128 + 2 * kp);
            acc0[i] = ffma2u(h.x, w0a, acc0[i]);
            acc0[i] = ffma2u(h.y, w1a, acc0[i]);
            acc1[i] = ffma2u(h.x, w0b, acc1[i]);
            acc1[i] = ffma2u(h.y, w1b, acc1[i]);
        }
    }
    float bva = b2[c0 + c];
    float bvb = b2[c0 + c + 64];
    #pragma unroll
    for (int i = 0; i < 16; i++) {
        int gr = r0 + eg * 16 + i;
        if (gr < nrows) {
            float2 ra = unpack2(acc0[i]);
            float2 rb = unpack2(acc1[i]);
            out[(size_t)gr * 1792 + c0 + c]      = ra.x + ra.y + bva;
            out[(size_t)gr * 1792 + c0 + c + 64] = rb.x + rb.y + bvb;
        }
    }
}

// biases = Hb @ Wb2 + bb2   (tiny: 14 cols)
__global__ void k_wb(const float* __restrict__ Wb, const float* __restrict__ bb,
                     int nrows, int which) {
    const float* H = which ? g_h_ij_b : g_h_ii_b;
    float* out = which ? g_b_ij : g_b_ii;
    int g = blockIdx.x * 256 + threadIdx.x;
    if (g >= nrows * 14) return;
    int r = g / 14, c = g - r * 14;
    float acc = bb[c];
    const float* h = H + (size_t)r * 128;
    for (int k = 0; k < 128; k++) acc += h[k] * Wb[k * 14 + c];
    out[g] = acc;
}

// ---------------- expansion: persistent multi-edge, cp.async double-buffer -
// Each block loops over edges; w3j staged once; next edge's w/x/b prefetched
// during current edge's compute. Buffer layout: [w 1792][x 1568][b 14][pad 2].
__global__ __launch_bounds__(256) void k_exp(int which, int n) {
    __shared__ float4 w3sh4[307];
    __shared__ float buf[2][3376];
    __shared__ float rsh[196];
    float* w3sh = (float*)w3sh4;
    int tid = threadIdx.x;
    for (int t = tid; t < 307; t += 256) w3sh4[t] = g_w3j4[t];

    const float* wbase = which ? g_w_ij : g_w_ii;
    const float* xbase = which ? g_x_ij : g_x_ii;
    const float* bbase = which ? g_b_ij : g_b_ii;
    float* rawbase = which ? g_raw_ij : g_raw_ii;

    unsigned bufa[2] = { smem_u32(buf[0]), smem_u32(buf[1]) };

    auto prefetch = [&](int e, int bi) {
        unsigned dst = bufa[bi];
        const float4* wr = (const float4*)(wbase + (size_t)e * 1792);
        const float4* xr = (const float4*)(xbase + (size_t)e * 1568);
        for (int t = tid; t < 840; t += 256) {
            if (t < 448) cp16(dst + t * 16, wr + t);
            else         cp16(dst + 7168 + (t - 448) * 16, xr + (t - 448));
        }
        if (tid < 14) cp4(dst + 13440 + tid * 4, bbase + (size_t)e * 14 + tid);
    };

    int e = blockIdx.x;
    if (e < n) prefetch(e, 0);
    CP_COMMIT();
    int cur = 0;
    for (; e < n; e += gridDim.x) {
        int en = e + gridDim.x;
        CP_WAIT0();
        __syncthreads();
        if (en < n) { prefetch(en, cur ^ 1); CP_COMMIT(); }
        const float* wsh = buf[cur];
        const float* xsh = buf[cur] + 1792;
        const float* bsh = buf[cur] + 3360;

        // stage A: 196 r-slots, each a 32-element dot
        if (tid < 196) {
            int rr = tid;
            int p = 18;
            while (rr < P_RO[p]) p--;
            int loc = rr - P_RO[p];
            int li = K_L3[p];
            int d = 2 * li + 1;
            int uv = loc / d, kk = loc - uv * d;
            int muv = c_MUL[P_J[p]] * c_MUL[P_K[p]];
            const float* wp = wsh + P_WI[p] + uv;
            const float* xp = xsh + c_XO[P_I[p]] + kk;
            float acc = 0.f;
            #pragma unroll 8
            for (int w = 0; w < 32; w++) acc += wp[w * muv] * xp[w * d];
            if (li == 0) acc += bsh[P_BO[p] + uv];
            rsh[rr] = acc * 0.03125f;              // fold 1/mi
        }
        __syncthreads();

        // stage B: 196 outputs
        if (tid < 196) {
            int o = tid;
            int row = o / 14, col = o - row * 14;
            int j, u, a;
            if (row < 3)      { j = 0; u = row; a = 0; }
            else if (row < 9) { j = 1; u = (row - 3) / 3; a = (row - 3) % 3; }
            else              { j = 2; u = 0; a = row - 9; }
            int k2, v, b2;
            if (col < 3)      { k2 = 0; v = col; b2 = 0; }
            else if (col < 9) { k2 = 1; v = (col - 3) / 3; b2 = (col - 3) % 3; }
            else              { k2 = 2; v = 0; b2 = col - 9; }
            float acc = 0.f;
            for (int p = 0; p < 19; p++) {
                if (P_J[p] != j || P_K[p] != k2) continue;
                int d = 2 * K_L3[p] + 1;
                int dk = 2 * k2 + 1;
                const float* w3 = w3sh + K_OFF[p] + (a * dk + b2) * d;
                const float* rp = rsh + P_RO[p] + (u * c_MUL[k2] + v) * d;
                for (int kk = 0; kk < d; kk++) acc += w3[kk] * rp[kk];
            }
            rawbase[(size_t)e * 196 + o] = acc;
        }
        __syncthreads();
        cur ^= 1;
    }
}

// ---------------- symmetrize + write output --------------------------------
__global__ void k_sym(float* __restrict__ out) {
    int g = blockIdx.x * 256 + threadIdx.x;
    const int DIAG = NN * 196;
    const int TOT = DIAG + EE * 196;
    if (g >= TOT) return;
    if (g < DIAG) {
        int b = g / 196, o = g - b * 196;
        int r = o / 14, c = o - r * 14;
        out[g] = 0.5f * (g_raw_ii[b * 196 + o] + g_raw_ii[b * 196 + c * 14 + r]);
    } else {
        int gg = g - DIAG;
        int e = gg / 196, o = gg - e * 196;
        int r = o / 14, c = o - r * 14;
        int s = e / 159, rm = e - s * 159;
        int d = rm + (rm >= s);
        int rev = d * 159 + (s < d ? s : s - 1);   // reverse-edge index
        out[g] = 0.5f * (g_raw_ij[(size_t)e * 196 + o] + g_raw_ij[(size_t)rev * 196 + c * 14 + r]);
    }
}

// ---------------- launch ----------------------------------------------------
extern "C" void kernel_launch(void* const* d_in, const int* in_sizes, int n_in,
                              void* d_out, int out_size) {
    const float* fii      = (const float*)d_in[0];
    const float* fij      = (const float*)d_in[1];
    const float* embed    = (const float*)d_in[2];
    // d_in[3] = edge_index_full (unused: full-graph structure is closed-form)
    const float* wii      = (const float*)d_in[4];
    const float* wij      = (const float*)d_in[5];
    const float* ii_fc_w1 = (const float*)d_in[6];
    const float* ii_fc_b1 = (const float*)d_in[7];
    const float* ii_fc_w2 = (const float*)d_in[8];
    const float* ii_fc_b2 = (const float*)d_in[9];
    const float* ii_fb_w1 = (const float*)d_in[10];
    const float* ii_fb_b1 = (const float*)d_in[11];
    const float* ii_fb_w2 = (const float*)d_in[12];
    const float* ii_fb_b2 = (const float*)d_in[13];
    const float* ij_fc_w1 = (const float*)d_in[14];
    const float* ij_fc_b1 = (const float*)d_in[15];
    const float* ij_fc_w2 = (const float*)d_in[16];
    const float* ij_fc_b2 = (const float*)d_in[17];
    const float* ij_fb_w1 = (const float*)d_in[18];
    const float* ij_fb_b1 = (const float*)d_in[19];
    const float* ij_fb_w2 = (const float*)d_in[20];
    const float* ij_fb_b2 = (const float*)d_in[21];
    float* out = (float*)d_out;

    const int O3_SMEM = (18432 + 8 * 3136) * 4;   // 174080 B dynamic smem
    const int W2_SMEM = 98304;                    // 96 KB dynamic smem
    cudaFuncSetAttribute(k_o3, cudaFuncAttributeMaxDynamicSharedMemorySize, O3_SMEM);
    cudaFuncSetAttribute(k_w2, cudaFuncAttributeMaxDynamicSharedMemorySize, W2_SMEM);

    dim3 gii((NN + 63) / 64, 14), gij((EE + 63) / 64, 14);

    // Capture slot = launch index 3 → k_mlp_ij (last unmeasured large kernel).
    k_wigner<<<19, 64>>>();
    k_o3<<<296, 224, O3_SMEM>>>(fij, wij, 1, EE);
    k_o3<<<40, 224, O3_SMEM>>>(fii, wii, 0, NN);
    k_mlp_ij<<<EE / 32, 256>>>(embed, ij_fc_w1, ij_fc_b1, ij_fb_w1, ij_fb_b1);  // ← captured
    k_mlp_ii<<<NN, 256>>>(embed, ii_fc_w1, ii_fc_b1, ii_fb_w1, ii_fb_b1);
    k_w2<<<gij, 256, W2_SMEM>>>(ij_fc_w2, ij_fc_b2, EE, 1);
    k_w2<<<gii, 256, W2_SMEM>>>(ii_fc_w2, ii_fc_b2, NN, 0);
    k_wb<<<(EE * 14 + 255) / 256, 256>>>(ij_fb_w2, ij_fb_b2, EE, 1);
    k_wb<<<(NN * 14 + 255) / 256, 256>>>(ii_fb_w2, ii_fb_b2, NN, 0);
    k_exp<<<1036, 256>>>(1, EE);
    k_exp<<<160, 256>>>(0, NN);
    k_sym<<<((NN + EE) * 196 + 255) / 256, 256>>>(out);
}

// round 17
// speedup vs baseline: 1.0475x; 1.0475x over previous
#include <cuda_runtime.h>
#include <math.h>

#define EE 25440
#define NN 160

typedef unsigned long long ull;

// ---------------- packed f32x2 helpers ----------------
__device__ __forceinline__ ull ffma2u(ull a, ull b, ull c) {
    ull d;
    asm("fma.rn.f32x2 %0, %1, %2, %3;" : "=l"(d) : "l"(a), "l"(b), "l"(c));
    return d;
}
__device__ __forceinline__ ull fdup(float v) {
    ull d;
    asm("mov.b64 %0, {%1, %1};" : "=l"(d) : "r"(__float_as_uint(v)));
    return d;
}
__device__ __forceinline__ ull fpack(float lo, float hi) {
    ull d;
    asm("mov.b64 %0, {%1, %2};" : "=l"(d) : "f"(lo), "f"(hi));
    return d;
}
__device__ __forceinline__ float2 unpack2(ull v) {
    float2 r;
    asm("mov.b64 {%0, %1}, %2;" : "=f"(r.x), "=f"(r.y) : "l"(v));
    return r;
}
__device__ __forceinline__ unsigned smem_u32(const void* p) {
    unsigned a;
    asm("{ .reg .u64 t; cvta.to.shared.u64 t, %1; cvt.u32.u64 %0, t; }" : "=r"(a) : "l"(p));
    return a;
}
__device__ __forceinline__ void cp16(unsigned dst, const void* src) {
    asm volatile("cp.async.ca.shared.global [%0], [%1], 16;" :: "r"(dst), "l"(src));
}
#define CP_COMMIT() asm volatile("cp.async.commit_group;" ::: "memory")
#define CP_WAIT0()  asm volatile("cp.async.wait_group 0;" ::: "memory")

// ---------------- device scratch (static, no runtime alloc) ----------------
__device__ float g_x_ii[NN * 1568];
__device__ float g_x_ij[(size_t)EE * 1568];
__device__ float g_h_ii_c[NN * 128], g_h_ii_b[NN * 128];
__device__ float g_h_ij_c[EE * 128], g_h_ij_b[EE * 128];
__device__ float g_w_ii[NN * 1792];
__device__ float g_w_ij[(size_t)EE * 1792];
__device__ float g_b_ii[NN * 14], g_b_ij[EE * 14];
__device__ float g_raw_ii[NN * 196];
__device__ float g_raw_ij[EE * 196];
__device__ float4 g_w3j4[307];     // 1228 floats (1225 used, padded for float4)

// ---------------- constant tables ----------------
// feature irreps: l = {0,1,1,2,2,3,3,4,4}
__constant__ int c_XO[10] = {0, 32, 128, 224, 384, 544, 768, 992, 1280, 1568};
__constant__ int c_FO[9]  = {0, 64, 256, 448, 768, 1088, 1536, 1984, 2560};
__constant__ int c_D[9]   = {1, 3, 3, 5, 5, 7, 7, 9, 9};
__constant__ int c_MUL[3] = {3, 2, 1};   // out irrep multiplicities (index = l)
// o3 task table: 4*d tasks per segment (o-octs), cumulative
__constant__ int c_TB8[10] = {0, 4, 16, 28, 48, 68, 96, 124, 160, 196};

// 19 expansion paths, in reference INSTR order
__constant__ int P_I[19]  = {0,0,0,1,1,1,1,2,2,3,3,4,4,4,4,5,5,6,8};
__constant__ int P_J[19]  = {0,1,2,0,1,1,2,1,2,1,2,0,1,2,2,1,2,2,2};
__constant__ int P_K[19]  = {0,1,2,1,0,2,1,1,2,2,1,2,1,0,2,2,1,2,2};
__constant__ int P_WI[19] = {0,288,416,448,640,832,896,960,1088,1120,1184,1248,1344,1472,1568,1600,1664,1728,1760};
__constant__ int P_RO[19] = {0,9,13,14,32,50,56,62,74,77,87,97,112,132,147,152,166,180,187};
__constant__ int P_BO[19] = {0,9,13,-1,-1,-1,-1,-1,-1,-1,-1,-1,-1,-1,-1,-1,-1,-1,-1};
// wigner tensor (lj,lk,li), flat offsets
__constant__ int K_OFF[19]= {0,1,10,35,44,53,98,143,170,245,320,395,420,465,490,615,720,825,1000};
__constant__ int K_L3[19] = {0,0,0,1,1,1,1,1,1,2,2,2,2,2,2,3,3,3,4};  // li per path
__constant__ int W_L1[19] = {0,1,2,0,1,1,2,1,2,1,2,0,1,2,2,1,2,2,2};  // lj per path
__constant__ int W_L2[19] = {0,1,2,1,0,2,1,1,2,2,1,2,1,0,2,2,1,2,2};  // lk per path

// ---------------- Wigner 3j on device (fp64, exact port of reference) -----
struct cplx { double re, im; };

__device__ __forceinline__ double dfac(int n) {
    double r = 1.0;
    for (int i = 2; i <= n; i++) r *= (double)i;
    return r;
}

__device__ double su2_cg(int j1, int m1, int j2, int m2, int j3, int m3) {
    int vmin = max(max(j2 - j1 + m3, m1 - j1), 0);
    int vmax = min(min(j2 + j3 + m1, j3 - j1 + j2), j3 + m3);
    if (vmax < vmin) return 0.0;
    double c = sqrt((2.0 * j3 + 1.0) * dfac(j3 + j1 - j2) * dfac(j3 - j1 + j2) * dfac(j1 + j2 - j3)
                    * dfac(j3 + m3) * dfac(j3 - m3)
                    / (dfac(j1 + j2 + j3 + 1) * dfac(j1 - m1) * dfac(j1 + m1)
                       * dfac(j2 - m2) * dfac(j2 + m2)));
    double s = 0.0;
    for (int v = vmin; v <= vmax; v++) {
        double t = dfac(j2 + j3 + m1 - v) * dfac(j1 - m1 + v)
                   / (dfac(v) * dfac(j3 - j1 + j2 - v) * dfac(j3 + m3 - v) * dfac(v + j1 - j2 - m3));
        s += (((v + j2 + m2) & 1) ? -t : t);
    }
    return c * s;
}

// q(l)[row][col] including the (-i)^l factor
__device__ cplx q_entry(int l, int row, int col) {
    int m = row - l;
    const double r2 = 0.70710678118654752440;
    double re = 0.0, im = 0.0;
    if (m < 0) {
        if (col == l - m) re = r2;
        else if (col == l + m) im = -r2;
    } else if (m == 0) {
        if (col == l) re = 1.0;
    } else {
        double sg = (m & 1) ? -1.0 : 1.0;
        if (col == l + m) re = sg * r2;
        else if (col == l - m) im = sg * r2;
    }
    double a = re, b = im;
    switch (l & 3) {              // multiply by (-i)^l
        case 0: break;
        case 1: { double t = a; a = b;  b = -t; } break;
        case 2: a = -a; b = -b; break;
        case 3: { double t = a; a = -b; b = t; } break;
    }
    cplx q; q.re = a; q.im = b; return q;
}

__global__ void k_wigner() {
    int p = blockIdx.x;
    int l1 = W_L1[p], l2 = W_L2[p], l3 = K_L3[p];
    int d1 = 2 * l1 + 1, d2 = 2 * l2 + 1, d3 = 2 * l3 + 1;
    int nout = d1 * d2 * d3;
    double inv = 1.0 / sqrt(2.0 * l3 + 1.0);
    float* w3 = (float*)g_w3j4;
    for (int o = threadIdx.x; o < nout; o += blockDim.x) {
        int j = o / (d2 * d3);
        int rem = o % (d2 * d3);
        int lc = rem / d3;
        int m = rem % d3;
        // q(l)[row][col] is nonzero only for row in {col, 2l-col}
        int ic[2] = { j, d1 - 1 - j };
        int kc[2] = { lc, d2 - 1 - lc };
        int ni = (ic[1] == ic[0]) ? 1 : 2;
        int nk = (kc[1] == kc[0]) ? 1 : 2;
        double acc = 0.0;
        for (int ii = 0; ii < ni; ii++)
            for (int kk = 0; kk < nk; kk++) {
                int i = ic[ii], k = kc[kk];
                int n = i + k - l1 - l2 + l3;     // m3 = m1 + m2
                if (n < 0 || n >= d3) continue;
                double cg = su2_cg(l1, i - l1, l2, k - l2, l3, i - l1 + k - l2);
                if (cg == 0.0) continue;
                cplx q1 = q_entry(l1, i, j);
                cplx q2 = q_entry(l2, k, lc);
                cplx q3 = q_entry(l3, n, m);
                q3.im = -q3.im;                   // conj
                double re12 = q1.re * q2.re - q1.im * q2.im;
                double im12 = q1.re * q2.im + q1.im * q2.re;
                double re = re12 * q3.re - im12 * q3.im;
                acc += re * cg;
            }
        w3[K_OFF[p] + o] = (float)(acc * inv);
    }
}

// ---------------- o3 linear: x = blockdiag(W) @ f * (1/8) ------------------
// Row-blocked R=4 (verified: 416 -> 246us): each W LDS.128 pair amortized
// over 4 rows; f row-blocks staged by cp.async, double-buffered.
__global__ __launch_bounds__(224) void k_o3(const float* __restrict__ f,
                                            const float* __restrict__ W,
                                            int which, int nrows) {
    extern __shared__ float sh[];
    float* Wsh = sh;                               // 18432 floats
    float* fb0 = sh + 18432;                       // 4*3136 floats
    float* fb1 = sh + 18432 + 4 * 3136;            // 4*3136 floats
    for (int t = threadIdx.x; t < 4608; t += 224)
        ((float4*)Wsh)[t] = ((const float4*)W)[t];
    float* xbase = which ? g_x_ij : g_x_ii;

    int t = threadIdx.x;
    int s = 0;
    if (t < 196) { while (s < 8 && t >= c_TB8[s + 1]) s++; }
    int loc = t - c_TB8[s];
    int q = loc & 3;          // o-oct
    int m = loc >> 2;
    int d = c_D[s];
    int foff = c_FO[s] + m;

    unsigned fba[2] = { smem_u32(fb0), smem_u32(fb1) };
    float* fbp[2] = { fb0, fb1 };

    // prefetch row-block rb into buffer bi (14 cp.async per thread)
    auto prefetch = [&](int rb, int bi) {
        unsigned base = fba[bi];
        #pragma unroll
        for (int i = 0; i < 14; i++) {
            int slot = t + i * 224;               // 0..3135
            int r = slot / 784, pos = slot - r * 784;
            int row = rb * 4 + r;
            if (row < nrows)
                cp16(base + r * 12544 + pos * 16,
                     (const float4*)(f + (size_t)row * 3136) + pos);
        }
    };

    int rb = blockIdx.x;
    prefetch(rb, 0);
    CP_COMMIT();
    CP_WAIT0();
    __syncthreads();
    int cur = 0;
    for (; rb * 4 < nrows; rb += gridDim.x) {
        int rbn = rb + gridDim.x;
        if (rbn * 4 < nrows) { prefetch(rbn, cur ^ 1); CP_COMMIT(); }
        if (t < 196) {
            const float* fc = fbp[cur];
            const ulonglong2* w2p = (const ulonglong2*)(Wsh + s * 2048) + q * 2;
            ull a00=0,a01=0,a02=0,a03=0, a10=0,a11=0,a12=0,a13=0;
            ull a20=0,a21=0,a22=0,a23=0, a30=0,a31=0,a32=0,a33=0;
            #pragma unroll 2
            for (int u = 0; u < 64; u++) {
                ulonglong2 wa = w2p[u * 8];
                ulonglong2 wb = w2p[u * 8 + 1];
                int fo = foff + u * d;
                ull f0 = fdup(fc[fo]);
                ull f1 = fdup(fc[3136 + fo]);
                ull f2 = fdup(fc[6272 + fo]);
                ull f3 = fdup(fc[9408 + fo]);
                a00 = ffma2u(f0, wa.x, a00); a01 = ffma2u(f0, wa.y, a01);
                a02 = ffma2u(f0, wb.x, a02); a03 = ffma2u(f0, wb.y, a03);
                a10 = ffma2u(f1, wa.x, a10); a11 = ffma2u(f1, wa.y, a11);
                a12 = ffma2u(f1, wb.x, a12); a13 = ffma2u(f1, wb.y, a13);
                a20 = ffma2u(f2, wa.x, a20); a21 = ffma2u(f2, wa.y, a21);
                a22 = ffma2u(f2, wb.x, a22); a23 = ffma2u(f2, wb.y, a23);
                a30 = ffma2u(f3, wa.x, a30); a31 = ffma2u(f3, wa.y, a31);
                a32 = ffma2u(f3, wb.x, a32); a33 = ffma2u(f3, wb.y, a33);
            }
            int o0 = q * 8;
            ull accs[4][4] = {{a00,a01,a02,a03},{a10,a11,a12,a13},
                              {a20,a21,a22,a23},{a30,a31,a32,a33}};
            #pragma unroll
            for (int r = 0; r < 4; r++) {
                int row = rb * 4 + r;
                if (row < nrows) {
                    float* xp = xbase + (size_t)row * 1568 + c_XO[s] + m;
                    float2 r0 = unpack2(accs[r][0]), r1 = unpack2(accs[r][1]);
                    float2 r2 = unpack2(accs[r][2]), r3 = unpack2(accs[r][3]);
                    xp[(o0 + 0) * d] = r0.x * 0.125f;
                    xp[(o0 + 1) * d] = r0.y * 0.125f;
                    xp[(o0 + 2) * d] = r1.x * 0.125f;
                    xp[(o0 + 3) * d] = r1.y * 0.125f;
                    xp[(o0 + 4) * d] = r2.x * 0.125f;
                    xp[(o0 + 5) * d] = r2.y * 0.125f;
                    xp[(o0 + 6) * d] = r3.x * 0.125f;
                    xp[(o0 + 7) * d] = r3.y * 0.125f;
                }
            }
        }
        CP_WAIT0();
        __syncthreads();
        cur ^= 1;
    }
}

// ---------------- MLP hidden layers ----------------------------------------
__device__ __forceinline__ float silu(float v) { return v / (1.f + expf(-v)); }

__global__ __launch_bounds__(256) void k_mlp_ii(const float* __restrict__ embed,
        const float* __restrict__ w1c, const float* __restrict__ b1c,
        const float* __restrict__ w1b, const float* __restrict__ b1b) {
    __shared__ float esh[128];
    int b = blockIdx.x;
    if (threadIdx.x < 128) esh[threadIdx.x] = embed[b * 128 + threadIdx.x];
    __syncthreads();
    int c = threadIdx.x & 127, sel = threadIdx.x >> 7;
    const float* Wm = sel ? w1b : w1c;
    float acc = (sel ? b1b : b1c)[c];
    for (int k = 0; k < 128; k++) acc += esh[k] * Wm[k * 128 + c];
    float* out = sel ? g_h_ii_b : g_h_ii_c;
    out[b * 128 + c] = silu(acc);
}

// 2 cols x 16 edges per thread: each broadcast Psh LDS.128 feeds 4 FFMA2
// (was 2), halving L1 wavefronts (k_mlp_ij measured L1=73.6% busy).
// Accumulation order per (edge, col) unchanged -> bit-identical results.
__global__ __launch_bounds__(256) void k_mlp_ij(const float* __restrict__ embed,
        const float* __restrict__ w1c, const float* __restrict__ b1c,
        const float* __restrict__ w1b, const float* __restrict__ b1b) {
    __shared__ float Psh[32][256];
    int e0 = blockIdx.x * 32;
    for (int idx = threadIdx.x; idx < 32 * 256; idx += 256) {
        int e = idx >> 8, k = idx & 255;
        int ge = e0 + e;
        int s = ge / 159, rm = ge - s * 159;
        int dn = rm + (rm >= s);
        Psh[e][k] = (k < 128) ? embed[s * 128 + k] : embed[dn * 128 + (k - 128)];
    }
    __syncthreads();
    int c = threadIdx.x & 63;
    int sel = (threadIdx.x >> 6) & 1;
    int eg = threadIdx.x >> 7;            // 0 or 1 (edge half)
    const float* Wm = sel ? w1b : w1c;
    float bva = (sel ? b1b : b1c)[c];
    float bvb = (sel ? b1b : b1c)[c + 64];
    ull acca[16], accb[16];
    #pragma unroll
    for (int e = 0; e < 16; e++) { acca[e] = 0ULL; accb[e] = 0ULL; }
    #pragma unroll 2
    for (int k = 0; k < 256; k += 4) {
        ull w0a = fpack(Wm[k * 128 + c],       Wm[(k + 1) * 128 + c]);
        ull w1a = fpack(Wm[(k + 2) * 128 + c], Wm[(k + 3) * 128 + c]);
        ull w0b = fpack(Wm[k * 128 + c + 64],       Wm[(k + 1) * 128 + c + 64]);
        ull w1b2 = fpack(Wm[(k + 2) * 128 + c + 64], Wm[(k + 3) * 128 + c + 64]);
        #pragma unroll
        for (int e = 0; e < 16; e++) {
            ulonglong2 p = *(const ulonglong2*)&Psh[eg * 16 + e][k];
            acca[e] = ffma2u(p.x, w0a, acca[e]);
            acca[e] = ffma2u(p.y, w1a, acca[e]);
            accb[e] = ffma2u(p.x, w0b, accb[e]);
            accb[e] = ffma2u(p.y, w1b2, accb[e]);
        }
    }
    float* out = sel ? g_h_ij_b : g_h_ij_c;
    #pragma unroll
    for (int e = 0; e < 16; e++) {
        int ge = e0 + eg * 16 + e;
        float2 ra = unpack2(acca[e]);
        float2 rb = unpack2(accb[e]);
        out[(size_t)ge * 128 + c]      = silu(ra.x + ra.y + bva);
        out[(size_t)ge * 128 + c + 64] = silu(rb.x + rb.y + bvb);
    }
}

// ---------------- second MLP layer: weights = H @ W2 + b2 ------------------
// Block 64 rows x 128 cols; thread = 16 rows x 2 cols.
__global__ __launch_bounds__(256) void k_w2(const float* __restrict__ W2,
                                            const float* __restrict__ b2,
                                            int nrows, int which) {
    extern __shared__ float s2[];
    float* Hsh = s2;                       // 64*128 floats (32 KB)
    ull* Wp = (ull*)(s2 + 64 * 128);       // [64 kp][128 c] packed pairs (64 KB)
    const float* H = which ? g_h_ij_c : g_h_ii_c;
    float* out = which ? g_w_ij : g_w_ii;
    int r0 = blockIdx.x * 64, c0 = blockIdx.y * 128;
    for (int idx = threadIdx.x; idx < 64 * 32; idx += 256) {
        int r = idx >> 5, qq = idx & 31;
        int gr = r0 + r;
        float4 v = make_float4(0.f, 0.f, 0.f, 0.f);
        if (gr < nrows) v = ((const float4*)(H + (size_t)gr * 128))[qq];
        ((float4*)(Hsh + r * 128))[qq] = v;
    }
    for (int idx = threadIdx.x; idx < 8192; idx += 256) {
        int kp = idx >> 7, c = idx & 127;
        float lo = W2[(size_t)(2 * kp) * 1792 + c0 + c];
        float hi = W2[(size_t)(2 * kp + 1) * 1792 + c0 + c];
        Wp[kp * 128 + c] = fpack(lo, hi);
    }
    __syncthreads();
    int c = threadIdx.x & 63, eg = threadIdx.x >> 6;
    ull acc0[16], acc1[16];
    #pragma unroll
    for (int i = 0; i < 16; i++) { acc0[i] = 0ULL; acc1[i] = 0ULL; }
    const float* hbase = Hsh + eg * 16 * 128;
    #pragma unroll 2
    for (int kp = 0; kp < 64; kp += 2) {
        ull w0a = Wp[kp * 128 + c];
        ull w1a = Wp[(kp + 1) * 128 + c];
        ull w0b = Wp[kp * 128 + c + 64];
        ull w1b = Wp[(kp + 1) * 128 + c + 64];
        #pragma unroll
        for (int i = 0; i < 16; i++) {
            ulonglong2 h = *(const ulonglong2*)(hbase + i * 128 + 2 * kp);
            acc0[i] = ffma2u(h.x, w0a, acc0[i]);
            acc0[i] = ffma2u(h.y, w1a, acc0[i]);
            acc1[i] = ffma2u(h.x, w0b, acc1[i]);
            acc1[i] = ffma2u(h.y, w1b, acc1[i]);
        }
    }
    float bva = b2[c0 + c];
    float bvb = b2[c0 + c + 64];
    #pragma unroll
    for (int i = 0; i < 16; i++) {
        int gr = r0 + eg * 16 + i;
        if (gr < nrows) {
            float2 ra = unpack2(acc0[i]);
            float2 rb = unpack2(acc1[i]);
            out[(size_t)gr * 1792 + c0 + c]      = ra.x + ra.y + bva;
            out[(size_t)gr * 1792 + c0 + c + 64] = rb.x + rb.y + bvb;
        }
    }
}

// biases = Hb @ Wb2 + bb2   (tiny: 14 cols)
__global__ void k_wb(const float* __restrict__ Wb, const float* __restrict__ bb,
                     int nrows, int which) {
    const float* H = which ? g_h_ij_b : g_h_ii_b;
    float* out = which ? g_b_ij : g_b_ii;
    int g = blockIdx.x * 256 + threadIdx.x;
    if (g >= nrows * 14) return;
    int r = g / 14, c = g - r * 14;
    float acc = bb[c];
    const float* h = H + (size_t)r * 128;
    for (int k = 0; k < 128; k++) acc += h[k] * Wb[k * 14 + c];
    out[g] = acc;
}

// ---------------- expansion (per-edge blocks; verified fastest form) -------
__global__ __launch_bounds__(256) void k_exp(int which) {
    __shared__ float wsh[1792];
    __shared__ float xsh[1568];
    __shared__ float4 w3sh4[307];
    __shared__ float rsh[196];
    __shared__ float bsh[14];
    float* w3sh = (float*)w3sh4;
    int b = blockIdx.x;
    int tid = threadIdx.x;
    const float4* wr = (const float4*)((which ? g_w_ij : g_w_ii) + (size_t)b * 1792);
    const float4* xr = (const float4*)((which ? g_x_ij : g_x_ii) + (size_t)b * 1568);
    const float* br = (which ? g_b_ij : g_b_ii) + (size_t)b * 14;
    for (int t = tid; t < 448; t += 256) ((float4*)wsh)[t] = wr[t];
    for (int t = tid; t < 392; t += 256) ((float4*)xsh)[t] = xr[t];
    for (int t = tid; t < 307; t += 256) w3sh4[t] = g_w3j4[t];
    if (tid < 14) bsh[tid] = br[tid];
    __syncthreads();

    // stage A: 196 r-slots, each a 32-element dot
    for (int rr = tid; rr < 196; rr += 256) {
        int p = 18;
        while (rr < P_RO[p]) p--;
        int loc = rr - P_RO[p];
        int li = K_L3[p];
        int d = 2 * li + 1;
        int uv = loc / d, kk = loc - uv * d;
        int muv = c_MUL[P_J[p]] * c_MUL[P_K[p]];
        const float* wp = wsh + P_WI[p] + uv;
        const float* xp = xsh + c_XO[P_I[p]] + kk;
        float acc = 0.f;
        #pragma unroll 8
        for (int w = 0; w < 32; w++) acc += wp[w * muv] * xp[w * d];
        if (li == 0) acc += bsh[P_BO[p] + uv];
        rsh[rr] = acc * 0.03125f;                  // fold 1/mi
    }
    __syncthreads();

    // stage B: 196 outputs
    float* raw = (which ? g_raw_ij : g_raw_ii) + (size_t)b * 196;
    for (int o = tid; o < 196; o += 256) {
        int row = o / 14, col = o - row * 14;
        int j, u, a;
        if (row < 3)      { j = 0; u = row; a = 0; }
        else if (row < 9) { j = 1; u = (row - 3) / 3; a = (row - 3) % 3; }
        else              { j = 2; u = 0; a = row - 9; }
        int k2, v, b2;
        if (col < 3)      { k2 = 0; v = col; b2 = 0; }
        else if (col < 9) { k2 = 1; v = (col - 3) / 3; b2 = (col - 3) % 3; }
        else              { k2 = 2; v = 0; b2 = col - 9; }
        float acc = 0.f;
        for (int p = 0; p < 19; p++) {
            if (P_J[p] != j || P_K[p] != k2) continue;
            int d = 2 * K_L3[p] + 1;
            int dk = 2 * k2 + 1;
            const float* w3 = w3sh + K_OFF[p] + (a * dk + b2) * d;
            const float* rp = rsh + P_RO[p] + (u * c_MUL[k2] + v) * d;
            for (int kk = 0; kk < d; kk++) acc += w3[kk] * rp[kk];
        }
        raw[o] = acc;
    }
}

// ---------------- symmetrize + write output --------------------------------
__global__ void k_sym(float* __restrict__ out) {
    int g = blockIdx.x * 256 + threadIdx.x;
    const int DIAG = NN * 196;
    const int TOT = DIAG + EE * 196;
    if (g >= TOT) return;
    if (g < DIAG) {
        int b = g / 196, o = g - b * 196;
        int r = o / 14, c = o - r * 14;
        out[g] = 0.5f * (g_raw_ii[b * 196 + o] + g_raw_ii[b * 196 + c * 14 + r]);
    } else {
        int gg = g - DIAG;
        int e = gg / 196, o = gg - e * 196;
        int r = o / 14, c = o - r * 14;
        int s = e / 159, rm = e - s * 159;
        int d = rm + (rm >= s);
        int rev = d * 159 + (s < d ? s : s - 1);   // reverse-edge index
        out[g] = 0.5f * (g_raw_ij[(size_t)e * 196 + o] + g_raw_ij[(size_t)rev * 196 + c * 14 + r]);
    }
}

// ---------------- launch ----------------------------------------------------
extern "C" void kernel_launch(void* const* d_in, const int* in_sizes, int n_in,
                              void* d_out, int out_size) {
    const float* fii      = (const float*)d_in[0];
    const float* fij      = (const float*)d_in[1];
    const float* embed    = (const float*)d_in[2];
    // d_in[3] = edge_index_full (unused: full-graph structure is closed-form)
    const float* wii      = (const float*)d_in[4];
    const float* wij      = (const float*)d_in[5];
    const float* ii_fc_w1 = (const float*)d_in[6];
    const float* ii_fc_b1 = (const float*)d_in[7];
    const float* ii_fc_w2 = (const float*)d_in[8];
    const float* ii_fc_b2 = (const float*)d_in[9];
    const float* ii_fb_w1 = (const float*)d_in[10];
    const float* ii_fb_b1 = (const float*)d_in[11];
    const float* ii_fb_w2 = (const float*)d_in[12];
    const float* ii_fb_b2 = (const float*)d_in[13];
    const float* ij_fc_w1 = (const float*)d_in[14];
    const float* ij_fc_b1 = (const float*)d_in[15];
    const float* ij_fc_w2 = (const float*)d_in[16];
    const float* ij_fc_b2 = (const float*)d_in[17];
    const float* ij_fb_w1 = (const float*)d_in[18];
    const float* ij_fb_b1 = (const float*)d_in[19];
    const float* ij_fb_w2 = (const float*)d_in[20];
    const float* ij_fb_b2 = (const float*)d_in[21];
    float* out = (float*)d_out;

    const int O3_SMEM = (18432 + 8 * 3136) * 4;   // 174080 B dynamic smem
    const int W2_SMEM = 98304;                    // 96 KB dynamic smem
    cudaFuncSetAttribute(k_o3, cudaFuncAttributeMaxDynamicSharedMemorySize, O3_SMEM);
    cudaFuncSetAttribute(k_w2, cudaFuncAttributeMaxDynamicSharedMemorySize, W2_SMEM);

    dim3 gii((NN + 63) / 64, 14), gij((EE + 63) / 64, 14);

    // Capture slot = launch index 3 → k_w2(ij) post 2-col fix.
    k_wigner<<<19, 64>>>();
    k_mlp_ij<<<EE / 32, 256>>>(embed, ij_fc_w1, ij_fc_b1, ij_fb_w1, ij_fb_b1);
    k_mlp_ii<<<NN, 256>>>(embed, ii_fc_w1, ii_fc_b1, ii_fb_w1, ii_fb_b1);
    k_w2<<<gij, 256, W2_SMEM>>>(ij_fc_w2, ij_fc_b2, EE, 1);   // ← captured
    k_w2<<<gii, 256, W2_SMEM>>>(ii_fc_w2, ii_fc_b2, NN, 0);
    k_o3<<<296, 224, O3_SMEM>>>(fij, wij, 1, EE);
    k_o3<<<40, 224, O3_SMEM>>>(fii, wii, 0, NN);
    k_wb<<<(EE * 14 + 255) / 256, 256>>>(ij_fb_w2, ij_fb_b2, EE, 1);
    k_wb<<<(NN * 14 + 255) / 256, 256>>>(ii_fb_w2, ii_fb_b2, NN, 0);
    k_exp<<<NN, 256>>>(0);
    k_exp<<<EE, 256>>>(1);
    k_sym<<<((NN + EE) * 196 + 255) / 256, 256>>>(out);
}